// round 12
// baseline (speedup 1.0000x reference)
#include <cuda_runtime.h>
#include <cstdint>
#include <cstddef>

#define Bn 128
#define Tn 1024
#define Dn 48
#define Hn 256
#define NBLK 128
#define NTHR 256

typedef unsigned long long ull;

// ---------------- device scratch (no allocations allowed) ----------------
__device__ float g_xT[Tn * Dn * Bn];                  // [t][48][b]
__device__ float g_o0[(size_t)Tn * 2 * Hn * Bn];      // [t][512][b]  layer0 outputs
__device__ float g_gx0[(size_t)Tn * 1024 * Bn];       // x-projection, dir 0 (incl. both biases)
__device__ float g_gx1[(size_t)Tn * 1024 * Bn];       // x-projection, dir 1
__device__ float g_hfin[2][8][4096];                  // final h: [dir][bg][j*16+b]

// ---------------- packed f32x2 helpers ----------------
__device__ __forceinline__ void ffma2(ull& d, ull a, ull b) {
    asm("fma.rn.f32x2 %0, %1, %2, %0;" : "+l"(d) : "l"(a), "l"(b));
}
__device__ __forceinline__ void fadd2(ull& d, ull a) {
    asm("add.rn.f32x2 %0, %0, %1;" : "+l"(d) : "l"(a));
}
__device__ __forceinline__ ull pack2(float a) {
    ull r;
    asm("mov.b64 %0, {%1, %1};" : "=l"(r) : "f"(a));
    return r;
}

// ---------------- cp.async helpers ----------------
__device__ __forceinline__ void cp_async16(void* smem_dst, const void* gsrc) {
    unsigned dst = (unsigned)__cvta_generic_to_shared(smem_dst);
    asm volatile("cp.async.cg.shared.global [%0], [%1], 16;" :: "r"(dst), "l"(gsrc) : "memory");
}
__device__ __forceinline__ void cp_commit() { asm volatile("cp.async.commit_group;" ::: "memory"); }
__device__ __forceinline__ void cp_wait0()  { asm volatile("cp.async.wait_group 0;"  ::: "memory"); }

// ---------------- cluster helpers ----------------
__device__ __forceinline__ unsigned smem_u32(const void* p) {
    return (unsigned)__cvta_generic_to_shared(p);
}
__device__ __forceinline__ void st_cluster_f32(unsigned laddr, unsigned rank, float v) {
    unsigned ra;
    asm volatile("mapa.shared::cluster.u32 %0, %1, %2;" : "=r"(ra) : "r"(laddr), "r"(rank));
    asm volatile("st.shared::cluster.f32 [%0], %1;" :: "r"(ra), "f"(v) : "memory");
}
#define CLUSTER_ARRIVE() asm volatile("barrier.cluster.arrive.aligned;" ::: "memory")
#define CLUSTER_WAIT()   asm volatile("barrier.cluster.wait.aligned;" ::: "memory")

// ---------------- transpose x ----------------
__global__ void transpose_x_kernel(const float* __restrict__ x) {
    int idx = blockIdx.x * blockDim.x + threadIdx.x;
    if (idx >= Tn * Dn * Bn) return;
    int b = idx & (Bn - 1);
    int rem = idx >> 7;
    int d = rem % Dn;
    int t = rem / Dn;
    g_xT[idx] = x[((size_t)b * Tn + t) * Dn + d];
}

__device__ __forceinline__ float sigmoidf_(float v) { return 1.0f / (1.0f + __expf(-v)); }

// ================= x-projection GEMM (retiled: 256 thr, thread = 4 rows x 16 b) =================
#define XP_SW_STRIDE 132
template<int K, int CHUNK, bool SRC_O0>
__global__ void __launch_bounds__(256) xproj_kernel(
    const float* __restrict__ Wf, const float* __restrict__ Wb,
    const float* __restrict__ bihf, const float* __restrict__ bhhf,
    const float* __restrict__ bihb, const float* __restrict__ bhhb)
{
    __shared__ float s_x[CHUNK * 128];
    __shared__ float s_w[CHUNK * XP_SW_STRIDE];

    const float* xin = SRC_O0 ? g_o0 : g_xT;     // device-side symbol resolution (ATS bug fix)

    const int t   = blockIdx.x;
    const int rt  = blockIdx.y;
    const int dir = blockIdx.z;
    const int tid = threadIdx.x;
    const int rg  = tid >> 3;              // 0..31, 4 rows each
    const int bgp = tid & 7;               // 0..7, 16 batches each

    const float* W   = dir ? Wb   : Wf;
    const float* bih = dir ? bihb : bihf;
    const float* bhh = dir ? bhhb : bhhf;
    float* gout = dir ? g_gx1 : g_gx0;

    ull acc[4][8];
#pragma unroll
    for (int u = 0; u < 4; ++u)
#pragma unroll
        for (int p = 0; p < 8; ++p) acc[u][p] = 0ull;

    // staging roles: row = tid&127, k-half = tid>>7
    const int wrow  = rt * 128 + (tid & 127);
    const int khalf = tid >> 7;

    for (int kc = 0; kc < K; kc += CHUNK) {
        const float* xsrc = xin + ((size_t)t * K + kc) * Bn;
        for (int i = tid; i < CHUNK * 32; i += 256)
            *(float4*)(s_x + i * 4) = *(const float4*)(xsrc + i * 4);
        {
            const float* wsrc = W + (size_t)wrow * K + kc + khalf * (CHUNK / 2);
#pragma unroll
            for (int k4 = 0; k4 < CHUNK / 8; ++k4) {
                float4 v = *(const float4*)(wsrc + k4 * 4);
                int kb = khalf * (CHUNK / 2) + k4 * 4;
                s_w[(kb + 0) * XP_SW_STRIDE + (tid & 127)] = v.x;
                s_w[(kb + 1) * XP_SW_STRIDE + (tid & 127)] = v.y;
                s_w[(kb + 2) * XP_SW_STRIDE + (tid & 127)] = v.z;
                s_w[(kb + 3) * XP_SW_STRIDE + (tid & 127)] = v.w;
            }
        }
        __syncthreads();

#pragma unroll 2
        for (int kk = 0; kk < CHUNK; ++kk) {
            float4 wv = *(const float4*)(s_w + kk * XP_SW_STRIDE + rg * 4);
            ull w0 = pack2(wv.x), w1 = pack2(wv.y), w2 = pack2(wv.z), w3 = pack2(wv.w);
            const float* xp = s_x + kk * 128 + bgp * 16;
            ull xv[8];
            // bgp-rotated 16B chunk order halves smem bank conflicts
#pragma unroll
            for (int q = 0; q < 4; ++q) {
                int ch = (q + bgp) & 3;
                ulonglong2 v = *(const ulonglong2*)(xp + ch * 4);
                xv[ch * 2]     = v.x;
                xv[ch * 2 + 1] = v.y;
            }
#define ROW(U, WV) \
            ffma2(acc[U][0], WV, xv[0]); ffma2(acc[U][1], WV, xv[1]); \
            ffma2(acc[U][2], WV, xv[2]); ffma2(acc[U][3], WV, xv[3]); \
            ffma2(acc[U][4], WV, xv[4]); ffma2(acc[U][5], WV, xv[5]); \
            ffma2(acc[U][6], WV, xv[6]); ffma2(acc[U][7], WV, xv[7]);
            ROW(0, w0) ROW(1, w1) ROW(2, w2) ROW(3, w3)
#undef ROW
        }
        __syncthreads();
    }

#pragma unroll
    for (int u = 0; u < 4; ++u) {
        int grow = rt * 128 + rg * 4 + u;
        ull bb = pack2(bih[grow] + bhh[grow]);
        float* dst = gout + ((size_t)t * 1024 + grow) * Bn + bgp * 16;
#pragma unroll
        for (int p = 0; p < 8; ++p) fadd2(acc[u][p], bb);
        *(ulonglong2*)(dst)      = make_ulonglong2(acc[u][0], acc[u][1]);
        *(ulonglong2*)(dst + 4)  = make_ulonglong2(acc[u][2], acc[u][3]);
        *(ulonglong2*)(dst + 8)  = make_ulonglong2(acc[u][4], acc[u][5]);
        *(ulonglong2*)(dst + 12) = make_ulonglong2(acc[u][6], acc[u][7]);
    }
}

// ================= recurrent phase: DSMEM cluster exchange =================
// 128 blocks, clusters of 8 (one cluster = (dir,bg); rank = hs).
// Each CTA holds the FULL h [256 k][16 b] in smem, double-buffered by parity.
// Pointwise writes its 512 values into all 8 CTAs' next-parity buffer via
// st.shared::cluster; one barrier.cluster per step replaces the L2 barrier.
// smem (floats): s_w [256 k][132]; s_h [2][256*16]; s_gx [128 r][16];
//                s_part [4 kg][128 r][16]; s_g [128 r][16]
#define RC_SW_STRIDE 132
#define RC_SW_FLOATS (256 * RC_SW_STRIDE)        // 33792
#define RC_SH_OFF    RC_SW_FLOATS
#define RC_SGX_OFF   (RC_SH_OFF + 2 * 4096)      // 41984
#define RC_SPART_OFF (RC_SGX_OFF + 2048)         // 44032
#define RC_SG_OFF    (RC_SPART_OFF + 8192)       // 52224
#define RC_SMEM_FLOATS (RC_SG_OFF + 2048)        // 54272 floats = 217088 B

template<bool L0P>
__global__ void __launch_bounds__(NTHR, 1) rec_kernel(
    const float* __restrict__ Whhf, const float* __restrict__ Whhb,
    const int* __restrict__ lengths)
{
    extern __shared__ float sm[];
    float* s_w    = sm;
    float* s_h    = sm + RC_SH_OFF;      // [2][4096]
    float* s_gx   = sm + RC_SGX_OFF;
    float* s_part = sm + RC_SPART_OFF;
    float* s_g    = sm + RC_SG_OFF;

    const int tid = threadIdx.x;
    const int dir = blockIdx.x >> 6;
    const int bg  = (blockIdx.x >> 3) & 7;
    const int hs  = blockIdx.x & 7;            // == cluster rank
    const int kg  = tid >> 6;
    const int lid = tid & 63;
    const int rg  = lid >> 2;                  // 0..15, 8 gate-rows each
    const int bq  = lid & 3;                   // 0..3

    const float* Whh = dir ? Whhb : Whhf;
    const float* gxb = dir ? g_gx1 : g_gx0;

    // ---- stage Whh slice: s_w[k][r] = Whh[grow(r)][k] ----
    for (int i = tid; i < 128 * 64; i += NTHR) {
        int r  = i >> 6;
        int k4 = (i & 63) * 4;
        int grow = (r >> 5) * Hn + hs * 32 + (r & 31);
        float4 v = *(const float4*)(Whh + (size_t)grow * Hn + k4);
        s_w[(k4 + 0) * RC_SW_STRIDE + r] = v.x;
        s_w[(k4 + 1) * RC_SW_STRIDE + r] = v.y;
        s_w[(k4 + 2) * RC_SW_STRIDE + r] = v.z;
        s_w[(k4 + 3) * RC_SW_STRIDE + r] = v.w;
    }
    // ---- zero h buffer 0 (step-0 input; local full copy) ----
    for (int i = tid; i < 1024; i += NTHR)
        *(float4*)(s_h + i * 4) = make_float4(0.f, 0.f, 0.f, 0.f);

    float c_reg[2] = {0.0f, 0.0f};
    float h_reg[2] = {0.0f, 0.0f};
    const int len = lengths[bg * 16 + (tid & 15)];
    const unsigned sh_u32 = smem_u32(s_h);

    // ---- prefetch gx for step 0 ----
    {
        int t0 = dir ? (Tn - 1) : 0;
        const float* gxrow = gxb + (size_t)t0 * 1024 * Bn;
        for (int i = tid; i < 512; i += NTHR) {
            int r = i >> 2, b4 = (i & 3) * 4;
            int grow = (r >> 5) * Hn + hs * 32 + (r & 31);
            cp_async16(s_gx + r * 16 + b4, gxrow + (size_t)grow * Bn + bg * 16 + b4);
        }
        cp_commit();
    }
    __syncthreads();

    for (int s = 0; s < Tn; ++s) {
        const int t = dir ? (Tn - 1 - s) : s;
        const float* hbuf = s_h + (s & 1) * 4096;

        // ---- gates partials over own k quarter (h already local in smem) ----
        ull acc[8][2];
#pragma unroll
        for (int u = 0; u < 8; ++u) { acc[u][0] = 0ull; acc[u][1] = 0ull; }

#pragma unroll 4
        for (int kk = 0; kk < 64; ++kk) {
            int k = kg * 64 + kk;
            float4 wa = *(const float4*)(s_w + k * RC_SW_STRIDE + rg * 8);
            float4 wb = *(const float4*)(s_w + k * RC_SW_STRIDE + rg * 8 + 4);
            ull w0 = pack2(wa.x), w1 = pack2(wa.y), w2 = pack2(wa.z), w3 = pack2(wa.w);
            ull w4 = pack2(wb.x), w5 = pack2(wb.y), w6 = pack2(wb.z), w7 = pack2(wb.w);
            ulonglong2 hp = *(const ulonglong2*)(hbuf + k * 16 + bq * 4);
            ffma2(acc[0][0], w0, hp.x); ffma2(acc[0][1], w0, hp.y);
            ffma2(acc[1][0], w1, hp.x); ffma2(acc[1][1], w1, hp.y);
            ffma2(acc[2][0], w2, hp.x); ffma2(acc[2][1], w2, hp.y);
            ffma2(acc[3][0], w3, hp.x); ffma2(acc[3][1], w3, hp.y);
            ffma2(acc[4][0], w4, hp.x); ffma2(acc[4][1], w4, hp.y);
            ffma2(acc[5][0], w5, hp.x); ffma2(acc[5][1], w5, hp.y);
            ffma2(acc[6][0], w6, hp.x); ffma2(acc[6][1], w6, hp.y);
            ffma2(acc[7][0], w7, hp.x); ffma2(acc[7][1], w7, hp.y);
        }

        // ---- store partials ----
#pragma unroll
        for (int u = 0; u < 8; ++u) {
            int r = rg * 8 + u;
            *(ulonglong2*)(s_part + (size_t)(kg * 128 + r) * 16 + bq * 4) =
                make_ulonglong2(acc[u][0], acc[u][1]);
        }
        __syncthreads();

        cp_wait0();              // gx for this step (committed last iteration)

        // ---- reduce k-groups + gx (biases folded into gx) ----
#pragma unroll
        for (int i = 0; i < 8; ++i) {
            int idx = tid + i * NTHR;
            s_g[idx] = s_gx[idx] + s_part[idx] + s_part[2048 + idx]
                     + s_part[4096 + idx] + s_part[6144 + idx];
        }
        __syncthreads();

        // ---- prefetch gx for step s+1 ----
        if (s + 1 < Tn) {
            int tn = dir ? (Tn - 2 - s) : (s + 1);
            const float* gxrow = gxb + (size_t)tn * 1024 * Bn;
            for (int i = tid; i < 512; i += NTHR) {
                int r = i >> 2, b4 = (i & 3) * 4;
                int grow = (r >> 5) * Hn + hs * 32 + (r & 31);
                cp_async16(s_gx + r * 16 + b4, gxrow + (size_t)grow * Bn + bg * 16 + b4);
            }
            cp_commit();
        }

        // ---- pointwise: cells tid, tid+256; broadcast h to all 8 CTAs' next buffer ----
        const unsigned nbase = sh_u32 + (((s + 1) & 1) * 4096 + hs * 512) * 4;
#pragma unroll
        for (int i = 0; i < 2; ++i) {
            int c = tid + i * NTHR;             // u = c>>4, b = c&15
            float ig = sigmoidf_(s_g[c]);
            float fg = sigmoidf_(s_g[512 + c]);
            float gg = tanhf    (s_g[1024 + c]);
            float og = sigmoidf_(s_g[1536 + c]);
            float cn = fg * c_reg[i] + ig * gg;
            float hn = og * tanhf(cn);
            bool m = (t < len);
            c_reg[i] = m ? cn : c_reg[i];
            float hw = m ? hn : h_reg[i];
            h_reg[i] = hw;
            unsigned laddr = nbase + c * 4;
#pragma unroll
            for (unsigned r = 0; r < 8; ++r)
                st_cluster_f32(laddr, r, hw);
            if (L0P)
                __stcg(&g_o0[((size_t)t * 512 + dir * Hn + hs * 32 + (c >> 4)) * Bn
                             + bg * 16 + (c & 15)], m ? hn : 0.0f);
            if (s == Tn - 1)
                __stcg(&g_hfin[dir][bg][(hs * 32 + (c >> 4)) * 16 + (c & 15)], hw);
        }

        // ---- one cluster barrier per step (orders DSMEM stores, syncs group) ----
        CLUSTER_ARRIVE();
        CLUSTER_WAIT();
    }
}

// ---------------- FC head ----------------
__global__ void head_kernel(const float* __restrict__ fc1_w, const float* __restrict__ fc1_b,
                            const float* __restrict__ fc2_w, const float* __restrict__ fc2_b,
                            float* __restrict__ out)
{
    __shared__ float s_h[2 * Hn];
    __shared__ float s_r[256];
    int b = blockIdx.x;
    int tid = threadIdx.x;
    int bg = b >> 4, bl = b & 15;
    for (int k = tid; k < 2 * Hn; k += 256) {
        int d = k >> 8;
        int j = k & (Hn - 1);
        s_h[k] = g_hfin[d][bg][j * 16 + bl];
    }
    __syncthreads();

    const float* wr = fc1_w + (size_t)tid * 2 * Hn;
    float sum = fc1_b[tid];
#pragma unroll 8
    for (int k = 0; k < 2 * Hn; ++k) sum += wr[k] * s_h[k];
    s_r[tid] = fmaxf(sum, 0.0f) * fc2_w[tid];
    __syncthreads();
    for (int st = 128; st > 0; st >>= 1) {
        if (tid < st) s_r[tid] += s_r[tid + st];
        __syncthreads();
    }
    if (tid == 0) out[b] = s_r[0] + fc2_b[0];
}

// ---------------- launch ----------------
static void launch_rec(void* func, const float* whf, const float* whb,
                       const int* lengths, int smem) {
    cudaLaunchConfig_t cfg = {};
    cfg.gridDim  = dim3(NBLK, 1, 1);
    cfg.blockDim = dim3(NTHR, 1, 1);
    cfg.dynamicSmemBytes = (size_t)smem;
    cudaLaunchAttribute attrs[1];
    attrs[0].id = cudaLaunchAttributeClusterDimension;
    attrs[0].val.clusterDim = {8, 1, 1};
    cfg.attrs = attrs;
    cfg.numAttrs = 1;
    using KT = void(*)(const float*, const float*, const int*);
    cudaLaunchKernelEx(&cfg, (KT)func, whf, whb, lengths);
}

extern "C" void kernel_launch(void* const* d_in, const int* in_sizes, int n_in,
                              void* d_out, int out_size)
{
    const float* x        = (const float*)d_in[0];
    const int*   lengths  = (const int*)  d_in[1];
    const float* w_ih_l0f = (const float*)d_in[2];
    const float* w_hh_l0f = (const float*)d_in[3];
    const float* b_ih_l0f = (const float*)d_in[4];
    const float* b_hh_l0f = (const float*)d_in[5];
    const float* w_ih_l0b = (const float*)d_in[6];
    const float* w_hh_l0b = (const float*)d_in[7];
    const float* b_ih_l0b = (const float*)d_in[8];
    const float* b_hh_l0b = (const float*)d_in[9];
    const float* w_ih_l1f = (const float*)d_in[10];
    const float* w_hh_l1f = (const float*)d_in[11];
    const float* b_ih_l1f = (const float*)d_in[12];
    const float* b_hh_l1f = (const float*)d_in[13];
    const float* w_ih_l1b = (const float*)d_in[14];
    const float* w_hh_l1b = (const float*)d_in[15];
    const float* b_ih_l1b = (const float*)d_in[16];
    const float* b_hh_l1b = (const float*)d_in[17];
    const float* fc1_w    = (const float*)d_in[18];
    const float* fc1_b    = (const float*)d_in[19];
    const float* fc2_w    = (const float*)d_in[20];
    const float* fc2_b    = (const float*)d_in[21];

    const int rec_smem = RC_SMEM_FLOATS * (int)sizeof(float);   // 217,088 B

    cudaFuncSetAttribute((const void*)rec_kernel<true>,
                         cudaFuncAttributeMaxDynamicSharedMemorySize, rec_smem);
    cudaFuncSetAttribute((const void*)rec_kernel<false>,
                         cudaFuncAttributeMaxDynamicSharedMemorySize, rec_smem);

    transpose_x_kernel<<<(Tn * Dn * Bn + 255) / 256, 256>>>(x);

    dim3 xpgrid(Tn, 8, 2);

    // layer-0 x-projection: g_xT -> g_gx
    xproj_kernel<48, 16, false><<<xpgrid, 256>>>(
        w_ih_l0f, w_ih_l0b, b_ih_l0f, b_hh_l0f, b_ih_l0b, b_hh_l0b);

    // layer-0 recurrence (cluster DSMEM h-exchange, writes g_o0)
    launch_rec((void*)rec_kernel<true>, w_hh_l0f, w_hh_l0b, lengths, rec_smem);

    // layer-1 x-projection: g_o0 -> g_gx
    xproj_kernel<512, 32, true><<<xpgrid, 256>>>(
        w_ih_l1f, w_ih_l1b, b_ih_l1f, b_hh_l1f, b_ih_l1b, b_hh_l1b);

    // layer-1 recurrence
    launch_rec((void*)rec_kernel<false>, w_hh_l1f, w_hh_l1b, lengths, rec_smem);

    head_kernel<<<Bn, 256>>>(fc1_w, fc1_b, fc2_w, fc2_b, (float*)d_out);
}

// round 13
// speedup vs baseline: 3.1281x; 3.1281x over previous
#include <cuda_runtime.h>
#include <cstdint>
#include <cstddef>

#define Bn 128
#define Tn 1024
#define Dn 48
#define Hn 256
#define NBLK 128
#define NTHR 256

typedef unsigned long long ull;

// ---------------- device scratch (no allocations allowed) ----------------
__device__ float g_xT[Tn * Dn * Bn];                  // [t][48][b]
__device__ float g_o0[(size_t)Tn * 2 * Hn * Bn];      // [t][512][b]  layer0 outputs
__device__ float g_gx0[(size_t)Tn * 1024 * Bn];       // x-projection, dir 0 (incl. both biases)
__device__ float g_gx1[(size_t)Tn * 1024 * Bn];       // x-projection, dir 1
__device__ float g_h[2][2][8][Hn * 16];               // [parity][dir][bg][k*16 + b]
__device__ unsigned g_cntg[16];
__device__ unsigned g_relg[16];

// ---------------- packed f32x2 helpers ----------------
__device__ __forceinline__ void ffma2(ull& d, ull a, ull b) {
    asm("fma.rn.f32x2 %0, %1, %2, %0;" : "+l"(d) : "l"(a), "l"(b));
}
__device__ __forceinline__ void fadd2(ull& d, ull a) {
    asm("add.rn.f32x2 %0, %0, %1;" : "+l"(d) : "l"(a));
}
__device__ __forceinline__ ull pack2(float a) {
    ull r;
    asm("mov.b64 %0, {%1, %1};" : "=l"(r) : "f"(a));
    return r;
}

// ---------------- cp.async helpers ----------------
__device__ __forceinline__ void cp_async16(void* smem_dst, const void* gsrc) {
    unsigned dst = (unsigned)__cvta_generic_to_shared(smem_dst);
    asm volatile("cp.async.cg.shared.global [%0], [%1], 16;" :: "r"(dst), "l"(gsrc) : "memory");
}
__device__ __forceinline__ void cp_commit() { asm volatile("cp.async.commit_group;" ::: "memory"); }
__device__ __forceinline__ void cp_wait0()  { asm volatile("cp.async.wait_group 0;"  ::: "memory"); }

// ---------------- acquire/release atomics ----------------
__device__ __forceinline__ unsigned atom_add_acqrel(unsigned* p, unsigned v) {
    unsigned old;
    asm volatile("atom.acq_rel.gpu.add.u32 %0, [%1], %2;"
                 : "=r"(old) : "l"(p), "r"(v) : "memory");
    return old;
}
__device__ __forceinline__ void st_relaxed(unsigned* p, unsigned v) {
    asm volatile("st.relaxed.gpu.u32 [%0], %1;" :: "l"(p), "r"(v) : "memory");
}
__device__ __forceinline__ void st_release(unsigned* p, unsigned v) {
    asm volatile("st.release.gpu.u32 [%0], %1;" :: "l"(p), "r"(v) : "memory");
}
__device__ __forceinline__ unsigned ld_acquire(unsigned* p) {
    unsigned v;
    asm volatile("ld.acquire.gpu.u32 %0, [%1];" : "=r"(v) : "l"(p) : "memory");
    return v;
}

// ---------------- group barrier (8 blocks; replay-safe monotonic release) ----------------
__device__ __forceinline__ void gbar_grp(int grp, unsigned& r_last) {
    __syncthreads();
    if (threadIdx.x == 0) {
        unsigned arrived = atom_add_acqrel(&g_cntg[grp], 1);
        if (arrived == 7) {
            st_relaxed(&g_cntg[grp], 0);
            st_release(&g_relg[grp], r_last + 1);
            r_last = r_last + 1;
        } else {
            unsigned cur;
            do { cur = ld_acquire(&g_relg[grp]); } while (cur == r_last);
            r_last = cur;
        }
    }
    __syncthreads();
}

// ---------------- transpose x ----------------
__global__ void transpose_x_kernel(const float* __restrict__ x) {
    int idx = blockIdx.x * blockDim.x + threadIdx.x;
    if (idx >= Tn * Dn * Bn) return;
    int b = idx & (Bn - 1);
    int rem = idx >> 7;
    int d = rem % Dn;
    int t = rem / Dn;
    g_xT[idx] = x[((size_t)b * Tn + t) * Dn + d];
}

__device__ __forceinline__ float sigmoidf_(float v) { return 1.0f / (1.0f + __expf(-v)); }

// ================= x-projection GEMM =================
// 256 threads/block, thread = 4 rows x 16 batch (64 f32x2 accs, ~110 regs ->
// 2 blocks/SM = 16 warps for latency cover). Inner loop is STRAIGHT-LINE,
// compile-time indices only (the r12 bgp-rotation caused a local-memory spill).
#define XP_SW_STRIDE 132
template<int K, int CHUNK, bool SRC_O0>
__global__ void __launch_bounds__(256) xproj_kernel(
    const float* __restrict__ Wf, const float* __restrict__ Wb,
    const float* __restrict__ bihf, const float* __restrict__ bhhf,
    const float* __restrict__ bihb, const float* __restrict__ bhhb)
{
    __shared__ float s_x[CHUNK * 128];
    __shared__ float s_w[CHUNK * XP_SW_STRIDE];

    const float* xin = SRC_O0 ? g_o0 : g_xT;     // device-side symbol resolution (ATS bug fix)

    const int t   = blockIdx.x;
    const int rt  = blockIdx.y;
    const int dir = blockIdx.z;
    const int tid = threadIdx.x;
    const int rg  = tid >> 3;              // 0..31, 4 rows each
    const int bgp = tid & 7;               // 0..7, 16 batches each

    const float* W   = dir ? Wb   : Wf;
    const float* bih = dir ? bihb : bihf;
    const float* bhh = dir ? bhhb : bhhf;
    float* gout = dir ? g_gx1 : g_gx0;

    ull acc[4][8];
#pragma unroll
    for (int u = 0; u < 4; ++u)
#pragma unroll
        for (int p = 0; p < 8; ++p) acc[u][p] = 0ull;

    // staging roles: row = tid&127, k-half = tid>>7
    const int wrow  = rt * 128 + (tid & 127);
    const int khalf = tid >> 7;

    for (int kc = 0; kc < K; kc += CHUNK) {
        const float* xsrc = xin + ((size_t)t * K + kc) * Bn;
        for (int i = tid; i < CHUNK * 32; i += 256)
            *(float4*)(s_x + i * 4) = *(const float4*)(xsrc + i * 4);
        {
            const float* wsrc = W + (size_t)wrow * K + kc + khalf * (CHUNK / 2);
#pragma unroll
            for (int k4 = 0; k4 < CHUNK / 8; ++k4) {
                float4 v = *(const float4*)(wsrc + k4 * 4);
                int kb = khalf * (CHUNK / 2) + k4 * 4;
                s_w[(kb + 0) * XP_SW_STRIDE + (tid & 127)] = v.x;
                s_w[(kb + 1) * XP_SW_STRIDE + (tid & 127)] = v.y;
                s_w[(kb + 2) * XP_SW_STRIDE + (tid & 127)] = v.z;
                s_w[(kb + 3) * XP_SW_STRIDE + (tid & 127)] = v.w;
            }
        }
        __syncthreads();

#pragma unroll 2
        for (int kk = 0; kk < CHUNK; ++kk) {
            float4 wv = *(const float4*)(s_w + kk * XP_SW_STRIDE + rg * 4);
            ull w0 = pack2(wv.x), w1 = pack2(wv.y), w2 = pack2(wv.z), w3 = pack2(wv.w);
            const float* xp = s_x + kk * 128 + bgp * 16;
            ulonglong2 x0 = *(const ulonglong2*)(xp);
            ulonglong2 x1 = *(const ulonglong2*)(xp + 4);
            ulonglong2 x2 = *(const ulonglong2*)(xp + 8);
            ulonglong2 x3 = *(const ulonglong2*)(xp + 12);
            ull xv[8] = {x0.x, x0.y, x1.x, x1.y, x2.x, x2.y, x3.x, x3.y};
#define ROW(U, WV) \
            ffma2(acc[U][0], WV, xv[0]); ffma2(acc[U][1], WV, xv[1]); \
            ffma2(acc[U][2], WV, xv[2]); ffma2(acc[U][3], WV, xv[3]); \
            ffma2(acc[U][4], WV, xv[4]); ffma2(acc[U][5], WV, xv[5]); \
            ffma2(acc[U][6], WV, xv[6]); ffma2(acc[U][7], WV, xv[7]);
            ROW(0, w0) ROW(1, w1) ROW(2, w2) ROW(3, w3)
#undef ROW
        }
        __syncthreads();
    }

#pragma unroll
    for (int u = 0; u < 4; ++u) {
        int grow = rt * 128 + rg * 4 + u;
        ull bb = pack2(bih[grow] + bhh[grow]);
        float* dst = gout + ((size_t)t * 1024 + grow) * Bn + bgp * 16;
#pragma unroll
        for (int p = 0; p < 8; ++p) fadd2(acc[u][p], bb);
        *(ulonglong2*)(dst)      = make_ulonglong2(acc[u][0], acc[u][1]);
        *(ulonglong2*)(dst + 4)  = make_ulonglong2(acc[u][2], acc[u][3]);
        *(ulonglong2*)(dst + 8)  = make_ulonglong2(acc[u][4], acc[u][5]);
        *(ulonglong2*)(dst + 12) = make_ulonglong2(acc[u][6], acc[u][7]);
    }
}

// ================= recurrent phase (r11-proven): (dir x bg x hs) partitioning =================
// 128 blocks: dir = bid>>6, bg = (bid>>3)&7 (16 batches), hs = bid&7 (32 units)
// barrier group = bid>>3 (8 blocks sharing (dir,bg))
// 256 threads: kg = tid>>6 (64 k each), rg = (tid&63)>>2 (8 gate-rows), bq = tid&3 (4 batches)
#define RC_SW_STRIDE 132
#define RC_SW_FLOATS (256 * RC_SW_STRIDE)       // 33792
#define RC_SH_OFF    RC_SW_FLOATS               // 4096
#define RC_SGX_OFF   (RC_SH_OFF + 4096)         // 2048
#define RC_SPART_OFF (RC_SGX_OFF + 2048)        // 8192
#define RC_SG_OFF    (RC_SPART_OFF + 8192)      // 2048
#define RC_SMEM_FLOATS (RC_SG_OFF + 2048)       // 50176 floats = 200704 B

template<bool L0P>
__global__ void __launch_bounds__(NTHR, 1) rec_kernel(
    const float* __restrict__ Whhf, const float* __restrict__ Whhb,
    const int* __restrict__ lengths)
{
    extern __shared__ float sm[];
    float* s_w    = sm;
    float* s_h    = sm + RC_SH_OFF;
    float* s_gx   = sm + RC_SGX_OFF;
    float* s_part = sm + RC_SPART_OFF;
    float* s_g    = sm + RC_SG_OFF;

    const int tid = threadIdx.x;
    const int dir = blockIdx.x >> 6;
    const int bg  = (blockIdx.x >> 3) & 7;
    const int hs  = blockIdx.x & 7;
    const int grp = blockIdx.x >> 3;
    const int kg  = tid >> 6;
    const int lid = tid & 63;
    const int rg  = lid >> 2;          // 0..15, 8 gate-rows each
    const int bq  = lid & 3;           // 0..3

    const float* Whh = dir ? Whhb : Whhf;
    const float* gxb = dir ? g_gx1 : g_gx0;

    // ---- stage Whh slice: s_w[k][r] = Whh[grow(r)][k] ----
    for (int i = tid; i < 128 * 64; i += NTHR) {
        int r  = i >> 6;
        int k4 = (i & 63) * 4;
        int grow = (r >> 5) * Hn + hs * 32 + (r & 31);
        float4 v = *(const float4*)(Whh + (size_t)grow * Hn + k4);
        s_w[(k4 + 0) * RC_SW_STRIDE + r] = v.x;
        s_w[(k4 + 1) * RC_SW_STRIDE + r] = v.y;
        s_w[(k4 + 2) * RC_SW_STRIDE + r] = v.z;
        s_w[(k4 + 3) * RC_SW_STRIDE + r] = v.w;
    }

    // ---- zero own g_h slice, both parities ----
#pragma unroll
    for (int i = 0; i < 2; ++i) {
        int c = tid + i * NTHR;
        __stcg(&g_h[0][dir][bg][hs * 512 + c], 0.0f);
        __stcg(&g_h[1][dir][bg][hs * 512 + c], 0.0f);
    }

    float c_reg[2] = {0.0f, 0.0f};
    float h_reg[2] = {0.0f, 0.0f};
    const int len = lengths[bg * 16 + (tid & 15)];

    unsigned r_last = ld_acquire(&g_relg[grp]);

    // ---- prefetch gx for step 0 ----
    {
        int t0 = dir ? (Tn - 1) : 0;
        const float* gxrow = gxb + (size_t)t0 * 1024 * Bn;
        for (int i = tid; i < 512; i += NTHR) {
            int r = i >> 2, b4 = (i & 3) * 4;
            int grow = (r >> 5) * Hn + hs * 32 + (r & 31);
            cp_async16(s_gx + r * 16 + b4, gxrow + (size_t)grow * Bn + bg * 16 + b4);
        }
        cp_commit();
    }

    gbar_grp(grp, r_last);

    for (int s = 0; s < Tn; ++s) {
        const int t = dir ? (Tn - 1 - s) : s;

        // ---- stage h [256 k][16 b] (contiguous 16 KB) ----
        {
            const float* hsrc = &g_h[s & 1][dir][bg][0];
            for (int i = tid; i < 1024; i += NTHR)
                cp_async16(s_h + i * 4, hsrc + i * 4);
            cp_commit();
        }
        cp_wait0();          // h + previously committed gx
        __syncthreads();

        // ---- gates partials over own k quarter ----
        ull acc[8][2];
#pragma unroll
        for (int u = 0; u < 8; ++u) { acc[u][0] = 0ull; acc[u][1] = 0ull; }

#pragma unroll 4
        for (int kk = 0; kk < 64; ++kk) {
            int k = kg * 64 + kk;
            float4 wa = *(const float4*)(s_w + k * RC_SW_STRIDE + rg * 8);
            float4 wb = *(const float4*)(s_w + k * RC_SW_STRIDE + rg * 8 + 4);
            ull w0 = pack2(wa.x), w1 = pack2(wa.y), w2 = pack2(wa.z), w3 = pack2(wa.w);
            ull w4 = pack2(wb.x), w5 = pack2(wb.y), w6 = pack2(wb.z), w7 = pack2(wb.w);
            ulonglong2 hp = *(const ulonglong2*)(s_h + k * 16 + bq * 4);
            ffma2(acc[0][0], w0, hp.x); ffma2(acc[0][1], w0, hp.y);
            ffma2(acc[1][0], w1, hp.x); ffma2(acc[1][1], w1, hp.y);
            ffma2(acc[2][0], w2, hp.x); ffma2(acc[2][1], w2, hp.y);
            ffma2(acc[3][0], w3, hp.x); ffma2(acc[3][1], w3, hp.y);
            ffma2(acc[4][0], w4, hp.x); ffma2(acc[4][1], w4, hp.y);
            ffma2(acc[5][0], w5, hp.x); ffma2(acc[5][1], w5, hp.y);
            ffma2(acc[6][0], w6, hp.x); ffma2(acc[6][1], w6, hp.y);
            ffma2(acc[7][0], w7, hp.x); ffma2(acc[7][1], w7, hp.y);
        }

        // ---- store partials: s_part[kg][r][b] ----
#pragma unroll
        for (int u = 0; u < 8; ++u) {
            int r = rg * 8 + u;
            *(ulonglong2*)(s_part + (size_t)(kg * 128 + r) * 16 + bq * 4) =
                make_ulonglong2(acc[u][0], acc[u][1]);
        }
        __syncthreads();

        // ---- reduce k-groups + gx (biases folded into gx) -> s_g ----
#pragma unroll
        for (int i = 0; i < 8; ++i) {
            int idx = tid + i * NTHR;
            s_g[idx] = s_gx[idx] + s_part[idx] + s_part[2048 + idx]
                     + s_part[4096 + idx] + s_part[6144 + idx];
        }
        __syncthreads();

        // ---- prefetch gx for step s+1 (independent of h/barrier) ----
        if (s + 1 < Tn) {
            int tn = dir ? (Tn - 2 - s) : (s + 1);
            const float* gxrow = gxb + (size_t)tn * 1024 * Bn;
            for (int i = tid; i < 512; i += NTHR) {
                int r = i >> 2, b4 = (i & 3) * 4;
                int grow = (r >> 5) * Hn + hs * 32 + (r & 31);
                cp_async16(s_gx + r * 16 + b4, gxrow + (size_t)grow * Bn + bg * 16 + b4);
            }
            cp_commit();
        }

        // ---- pointwise: cells tid and tid+256 ----
#pragma unroll
        for (int i = 0; i < 2; ++i) {
            int c = tid + i * NTHR;             // u = c>>4, b = c&15
            float ig = sigmoidf_(s_g[c]);
            float fg = sigmoidf_(s_g[512 + c]);
            float gg = tanhf    (s_g[1024 + c]);
            float og = sigmoidf_(s_g[1536 + c]);
            float cn = fg * c_reg[i] + ig * gg;
            float hn = og * tanhf(cn);
            bool m = (t < len);
            c_reg[i] = m ? cn : c_reg[i];
            float hw = m ? hn : h_reg[i];
            h_reg[i] = hw;
            __stcg(&g_h[(s + 1) & 1][dir][bg][hs * 512 + c], hw);
            if (L0P)
                __stcg(&g_o0[((size_t)t * 512 + dir * Hn + hs * 32 + (c >> 4)) * Bn
                             + bg * 16 + (c & 15)], m ? hn : 0.0f);
        }

        gbar_grp(grp, r_last);
    }
}

// ---------------- FC head ----------------
__global__ void head_kernel(const float* __restrict__ fc1_w, const float* __restrict__ fc1_b,
                            const float* __restrict__ fc2_w, const float* __restrict__ fc2_b,
                            float* __restrict__ out)
{
    __shared__ float s_h[2 * Hn];
    __shared__ float s_r[256];
    int b = blockIdx.x;
    int tid = threadIdx.x;
    int bg = b >> 4, bl = b & 15;
    // final L1 states: 1024 steps -> parity 0
    for (int k = tid; k < 2 * Hn; k += 256) {
        int d = k >> 8;
        int j = k & (Hn - 1);
        s_h[k] = g_h[0][d][bg][j * 16 + bl];
    }
    __syncthreads();

    const float* wr = fc1_w + (size_t)tid * 2 * Hn;
    float sum = fc1_b[tid];
#pragma unroll 8
    for (int k = 0; k < 2 * Hn; ++k) sum += wr[k] * s_h[k];
    s_r[tid] = fmaxf(sum, 0.0f) * fc2_w[tid];
    __syncthreads();
    for (int st = 128; st > 0; st >>= 1) {
        if (tid < st) s_r[tid] += s_r[tid + st];
        __syncthreads();
    }
    if (tid == 0) out[b] = s_r[0] + fc2_b[0];
}

// ---------------- launch ----------------
extern "C" void kernel_launch(void* const* d_in, const int* in_sizes, int n_in,
                              void* d_out, int out_size)
{
    const float* x        = (const float*)d_in[0];
    const int*   lengths  = (const int*)  d_in[1];
    const float* w_ih_l0f = (const float*)d_in[2];
    const float* w_hh_l0f = (const float*)d_in[3];
    const float* b_ih_l0f = (const float*)d_in[4];
    const float* b_hh_l0f = (const float*)d_in[5];
    const float* w_ih_l0b = (const float*)d_in[6];
    const float* w_hh_l0b = (const float*)d_in[7];
    const float* b_ih_l0b = (const float*)d_in[8];
    const float* b_hh_l0b = (const float*)d_in[9];
    const float* w_ih_l1f = (const float*)d_in[10];
    const float* w_hh_l1f = (const float*)d_in[11];
    const float* b_ih_l1f = (const float*)d_in[12];
    const float* b_hh_l1f = (const float*)d_in[13];
    const float* w_ih_l1b = (const float*)d_in[14];
    const float* w_hh_l1b = (const float*)d_in[15];
    const float* b_ih_l1b = (const float*)d_in[16];
    const float* b_hh_l1b = (const float*)d_in[17];
    const float* fc1_w    = (const float*)d_in[18];
    const float* fc1_b    = (const float*)d_in[19];
    const float* fc2_w    = (const float*)d_in[20];
    const float* fc2_b    = (const float*)d_in[21];

    const int rec_smem = RC_SMEM_FLOATS * (int)sizeof(float);   // 200,704 B

    cudaFuncSetAttribute((const void*)rec_kernel<true>,
                         cudaFuncAttributeMaxDynamicSharedMemorySize, rec_smem);
    cudaFuncSetAttribute((const void*)rec_kernel<false>,
                         cudaFuncAttributeMaxDynamicSharedMemorySize, rec_smem);

    transpose_x_kernel<<<(Tn * Dn * Bn + 255) / 256, 256>>>(x);

    dim3 xpgrid(Tn, 8, 2);

    // layer-0 x-projection: g_xT -> g_gx
    xproj_kernel<48, 16, false><<<xpgrid, 256>>>(
        w_ih_l0f, w_ih_l0b, b_ih_l0f, b_hh_l0f, b_ih_l0b, b_hh_l0b);

    // layer-0 recurrence (h-only, consumes gx, writes g_o0)
    rec_kernel<true><<<NBLK, NTHR, rec_smem>>>(w_hh_l0f, w_hh_l0b, lengths);

    // layer-1 x-projection: g_o0 -> g_gx
    xproj_kernel<512, 32, true><<<xpgrid, 256>>>(
        w_ih_l1f, w_ih_l1b, b_ih_l1f, b_hh_l1f, b_ih_l1b, b_hh_l1b);

    // layer-1 recurrence (h-only, consumes gx)
    rec_kernel<false><<<NBLK, NTHR, rec_smem>>>(w_hh_l1f, w_hh_l1b, lengths);

    head_kernel<<<Bn, 256>>>(fc1_w, fc1_b, fc2_w, fc2_b, (float*)d_out);
}

// round 14
// speedup vs baseline: 5.0172x; 1.6039x over previous
#include <cuda_runtime.h>
#include <cstdint>
#include <cstddef>

#define Bn 128
#define Tn 1024
#define Dn 48
#define Hn 256
#define NBLK 128
#define NTHR 256

typedef unsigned long long ull;

// ---------------- device scratch (no allocations allowed) ----------------
__device__ float g_xT[Tn * Dn * Bn];                  // [t][48][b]
__device__ float g_o0[(size_t)Tn * 2 * Hn * Bn];      // [t][512][b]  layer0 outputs
__device__ float g_gx0[(size_t)Tn * 1024 * Bn];       // x-projection, dir 0 (incl. both biases)
__device__ float g_gx1[(size_t)Tn * 1024 * Bn];       // x-projection, dir 1
__device__ float g_h[2][2][8][Hn * 16];               // [parity][dir][bg][k*16 + b]
__device__ unsigned g_cntg[16];
__device__ unsigned g_relg[16];

// ---------------- packed f32x2 helpers ----------------
__device__ __forceinline__ void ffma2(ull& d, ull a, ull b) {
    asm("fma.rn.f32x2 %0, %1, %2, %0;" : "+l"(d) : "l"(a), "l"(b));
}
__device__ __forceinline__ void fadd2(ull& d, ull a) {
    asm("add.rn.f32x2 %0, %0, %1;" : "+l"(d) : "l"(a));
}
__device__ __forceinline__ ull pack2(float a) {
    ull r;
    asm("mov.b64 %0, {%1, %1};" : "=l"(r) : "f"(a));
    return r;
}

// ---------------- cp.async helpers ----------------
__device__ __forceinline__ void cp_async16(void* smem_dst, const void* gsrc) {
    unsigned dst = (unsigned)__cvta_generic_to_shared(smem_dst);
    asm volatile("cp.async.cg.shared.global [%0], [%1], 16;" :: "r"(dst), "l"(gsrc) : "memory");
}
__device__ __forceinline__ void cp_commit() { asm volatile("cp.async.commit_group;" ::: "memory"); }
__device__ __forceinline__ void cp_wait0()  { asm volatile("cp.async.wait_group 0;"  ::: "memory"); }

// ---------------- acquire/release atomics ----------------
__device__ __forceinline__ unsigned atom_add_acqrel(unsigned* p, unsigned v) {
    unsigned old;
    asm volatile("atom.acq_rel.gpu.add.u32 %0, [%1], %2;"
                 : "=r"(old) : "l"(p), "r"(v) : "memory");
    return old;
}
__device__ __forceinline__ void st_relaxed(unsigned* p, unsigned v) {
    asm volatile("st.relaxed.gpu.u32 [%0], %1;" :: "l"(p), "r"(v) : "memory");
}
__device__ __forceinline__ void st_release(unsigned* p, unsigned v) {
    asm volatile("st.release.gpu.u32 [%0], %1;" :: "l"(p), "r"(v) : "memory");
}
__device__ __forceinline__ unsigned ld_acquire(unsigned* p) {
    unsigned v;
    asm volatile("ld.acquire.gpu.u32 %0, [%1];" : "=r"(v) : "l"(p) : "memory");
    return v;
}

// ---------------- group barrier (8 blocks; replay-safe monotonic release) ----------------
__device__ __forceinline__ void gbar_grp(int grp, unsigned& r_last) {
    __syncthreads();
    if (threadIdx.x == 0) {
        unsigned arrived = atom_add_acqrel(&g_cntg[grp], 1);
        if (arrived == 7) {
            st_relaxed(&g_cntg[grp], 0);
            st_release(&g_relg[grp], r_last + 1);
            r_last = r_last + 1;
        } else {
            unsigned cur;
            do { cur = ld_acquire(&g_relg[grp]); } while (cur == r_last);
            r_last = cur;
        }
    }
    __syncthreads();
}

// ---------------- transpose x ----------------
__global__ void transpose_x_kernel(const float* __restrict__ x) {
    int idx = blockIdx.x * blockDim.x + threadIdx.x;
    if (idx >= Tn * Dn * Bn) return;
    int b = idx & (Bn - 1);
    int rem = idx >> 7;
    int d = rem % Dn;
    int t = rem / Dn;
    g_xT[idx] = x[((size_t)b * Tn + t) * Dn + d];
}

__device__ __forceinline__ float sigmoidf_(float v) { return 1.0f / (1.0f + __expf(-v)); }

// ================= x-projection GEMM (r11 config + conflict-free padded s_x) =================
// 128 threads, thread = 8 rows x 16 batch. s_x layout [8 bgp][CHUNK*16 + 4]:
// the +4-float pad shifts each bgp block by 4 banks, so the warp's 8 x-chunks
// hit banks {0-3},{4-7},...,{28-31} -> conflict-free (was 4-way at stride 64B).
#define XP_SW_STRIDE 132
#define XP_XPAD(CH) ((CH) * 16 + 4)
template<int K, int CHUNK, bool SRC_O0>
__global__ void __launch_bounds__(128) xproj_kernel(
    const float* __restrict__ Wf, const float* __restrict__ Wb,
    const float* __restrict__ bihf, const float* __restrict__ bhhf,
    const float* __restrict__ bihb, const float* __restrict__ bhhb)
{
    __shared__ float s_x[8 * XP_XPAD(CHUNK)];
    __shared__ float s_w[CHUNK * XP_SW_STRIDE];

    const float* xin = SRC_O0 ? g_o0 : g_xT;     // device-side symbol resolution (ATS bug fix)

    const int t   = blockIdx.x;
    const int rt  = blockIdx.y;
    const int dir = blockIdx.z;
    const int tid = threadIdx.x;
    const int rg  = tid >> 3;              // 0..15, 8 rows each
    const int bgp = tid & 7;               // 0..7, 16 batches each

    const float* W   = dir ? Wb   : Wf;
    const float* bih = dir ? bihb : bihf;
    const float* bhh = dir ? bhhb : bhhf;
    float* gout = dir ? g_gx1 : g_gx0;

    ull acc[8][8];
#pragma unroll
    for (int u = 0; u < 8; ++u)
#pragma unroll
        for (int p = 0; p < 8; ++p) acc[u][p] = 0ull;

    const int wrow = rt * 128 + tid;           // this thread stages one W row
    for (int kc = 0; kc < K; kc += CHUNK) {
        // stage x chunk into padded per-bgp layout: s_x[g][kk*16 + off]
        const float* xsrc = xin + ((size_t)t * K + kc) * Bn;
        for (int i = tid; i < CHUNK * 32; i += 128) {
            int kk = i >> 5;
            int b4 = (i & 31) * 4;
            float4 v = *(const float4*)(xsrc + kk * Bn + b4);
            *(float4*)(s_x + (b4 >> 4) * XP_XPAD(CHUNK) + kk * 16 + (b4 & 15)) = v;
        }
        // stage W chunk [CHUNK][132] (transpose scatter)
        {
            const float* wsrc = W + (size_t)wrow * K + kc;
#pragma unroll
            for (int k4 = 0; k4 < CHUNK / 4; ++k4) {
                float4 v = *(const float4*)(wsrc + k4 * 4);
                s_w[(k4 * 4 + 0) * XP_SW_STRIDE + tid] = v.x;
                s_w[(k4 * 4 + 1) * XP_SW_STRIDE + tid] = v.y;
                s_w[(k4 * 4 + 2) * XP_SW_STRIDE + tid] = v.z;
                s_w[(k4 * 4 + 3) * XP_SW_STRIDE + tid] = v.w;
            }
        }
        __syncthreads();

#pragma unroll 2
        for (int kk = 0; kk < CHUNK; ++kk) {
            float4 wa = *(const float4*)(s_w + kk * XP_SW_STRIDE + rg * 8);
            float4 wb = *(const float4*)(s_w + kk * XP_SW_STRIDE + rg * 8 + 4);
            ull w0 = pack2(wa.x), w1 = pack2(wa.y), w2 = pack2(wa.z), w3 = pack2(wa.w);
            ull w4 = pack2(wb.x), w5 = pack2(wb.y), w6 = pack2(wb.z), w7 = pack2(wb.w);
            const float* xp = s_x + bgp * XP_XPAD(CHUNK) + kk * 16;
            ulonglong2 x0 = *(const ulonglong2*)(xp);
            ulonglong2 x1 = *(const ulonglong2*)(xp + 4);
            ulonglong2 x2 = *(const ulonglong2*)(xp + 8);
            ulonglong2 x3 = *(const ulonglong2*)(xp + 12);
            ull xv[8] = {x0.x, x0.y, x1.x, x1.y, x2.x, x2.y, x3.x, x3.y};
#define ROW(U, WV) \
            ffma2(acc[U][0], WV, xv[0]); ffma2(acc[U][1], WV, xv[1]); \
            ffma2(acc[U][2], WV, xv[2]); ffma2(acc[U][3], WV, xv[3]); \
            ffma2(acc[U][4], WV, xv[4]); ffma2(acc[U][5], WV, xv[5]); \
            ffma2(acc[U][6], WV, xv[6]); ffma2(acc[U][7], WV, xv[7]);
            ROW(0, w0) ROW(1, w1) ROW(2, w2) ROW(3, w3)
            ROW(4, w4) ROW(5, w5) ROW(6, w6) ROW(7, w7)
#undef ROW
        }
        __syncthreads();
    }

#pragma unroll
    for (int u = 0; u < 8; ++u) {
        int grow = rt * 128 + rg * 8 + u;
        ull bb = pack2(bih[grow] + bhh[grow]);
        float* dst = gout + ((size_t)t * 1024 + grow) * Bn + bgp * 16;
#pragma unroll
        for (int p = 0; p < 8; ++p) fadd2(acc[u][p], bb);
        *(ulonglong2*)(dst)      = make_ulonglong2(acc[u][0], acc[u][1]);
        *(ulonglong2*)(dst + 4)  = make_ulonglong2(acc[u][2], acc[u][3]);
        *(ulonglong2*)(dst + 8)  = make_ulonglong2(acc[u][4], acc[u][5]);
        *(ulonglong2*)(dst + 12) = make_ulonglong2(acc[u][6], acc[u][7]);
    }
}

// ================= recurrent phase (r11-proven, verbatim) =================
#define RC_SW_STRIDE 132
#define RC_SW_FLOATS (256 * RC_SW_STRIDE)       // 33792
#define RC_SH_OFF    RC_SW_FLOATS
#define RC_SGX_OFF   (RC_SH_OFF + 4096)
#define RC_SPART_OFF (RC_SGX_OFF + 2048)
#define RC_SG_OFF    (RC_SPART_OFF + 8192)
#define RC_SMEM_FLOATS (RC_SG_OFF + 2048)       // 50176 floats = 200704 B

template<bool L0P>
__global__ void __launch_bounds__(NTHR, 1) rec_kernel(
    const float* __restrict__ Whhf, const float* __restrict__ Whhb,
    const int* __restrict__ lengths)
{
    extern __shared__ float sm[];
    float* s_w    = sm;
    float* s_h    = sm + RC_SH_OFF;
    float* s_gx   = sm + RC_SGX_OFF;
    float* s_part = sm + RC_SPART_OFF;
    float* s_g    = sm + RC_SG_OFF;

    const int tid = threadIdx.x;
    const int dir = blockIdx.x >> 6;
    const int bg  = (blockIdx.x >> 3) & 7;
    const int hs  = blockIdx.x & 7;
    const int grp = blockIdx.x >> 3;
    const int kg  = tid >> 6;
    const int lid = tid & 63;
    const int rg  = lid >> 2;          // 0..15, 8 gate-rows each
    const int bq  = lid & 3;           // 0..3

    const float* Whh = dir ? Whhb : Whhf;
    const float* gxb = dir ? g_gx1 : g_gx0;

    // ---- stage Whh slice: s_w[k][r] = Whh[grow(r)][k] ----
    for (int i = tid; i < 128 * 64; i += NTHR) {
        int r  = i >> 6;
        int k4 = (i & 63) * 4;
        int grow = (r >> 5) * Hn + hs * 32 + (r & 31);
        float4 v = *(const float4*)(Whh + (size_t)grow * Hn + k4);
        s_w[(k4 + 0) * RC_SW_STRIDE + r] = v.x;
        s_w[(k4 + 1) * RC_SW_STRIDE + r] = v.y;
        s_w[(k4 + 2) * RC_SW_STRIDE + r] = v.z;
        s_w[(k4 + 3) * RC_SW_STRIDE + r] = v.w;
    }

    // ---- zero own g_h slice, both parities ----
#pragma unroll
    for (int i = 0; i < 2; ++i) {
        int c = tid + i * NTHR;
        __stcg(&g_h[0][dir][bg][hs * 512 + c], 0.0f);
        __stcg(&g_h[1][dir][bg][hs * 512 + c], 0.0f);
    }

    float c_reg[2] = {0.0f, 0.0f};
    float h_reg[2] = {0.0f, 0.0f};
    const int len = lengths[bg * 16 + (tid & 15)];

    unsigned r_last = ld_acquire(&g_relg[grp]);

    // ---- prefetch gx for step 0 ----
    {
        int t0 = dir ? (Tn - 1) : 0;
        const float* gxrow = gxb + (size_t)t0 * 1024 * Bn;
        for (int i = tid; i < 512; i += NTHR) {
            int r = i >> 2, b4 = (i & 3) * 4;
            int grow = (r >> 5) * Hn + hs * 32 + (r & 31);
            cp_async16(s_gx + r * 16 + b4, gxrow + (size_t)grow * Bn + bg * 16 + b4);
        }
        cp_commit();
    }

    gbar_grp(grp, r_last);

    for (int s = 0; s < Tn; ++s) {
        const int t = dir ? (Tn - 1 - s) : s;

        // ---- stage h [256 k][16 b] (contiguous 16 KB) ----
        {
            const float* hsrc = &g_h[s & 1][dir][bg][0];
            for (int i = tid; i < 1024; i += NTHR)
                cp_async16(s_h + i * 4, hsrc + i * 4);
            cp_commit();
        }
        cp_wait0();          // h + previously committed gx
        __syncthreads();

        // ---- gates partials over own k quarter ----
        ull acc[8][2];
#pragma unroll
        for (int u = 0; u < 8; ++u) { acc[u][0] = 0ull; acc[u][1] = 0ull; }

#pragma unroll 4
        for (int kk = 0; kk < 64; ++kk) {
            int k = kg * 64 + kk;
            float4 wa = *(const float4*)(s_w + k * RC_SW_STRIDE + rg * 8);
            float4 wb = *(const float4*)(s_w + k * RC_SW_STRIDE + rg * 8 + 4);
            ull w0 = pack2(wa.x), w1 = pack2(wa.y), w2 = pack2(wa.z), w3 = pack2(wa.w);
            ull w4 = pack2(wb.x), w5 = pack2(wb.y), w6 = pack2(wb.z), w7 = pack2(wb.w);
            ulonglong2 hp = *(const ulonglong2*)(s_h + k * 16 + bq * 4);
            ffma2(acc[0][0], w0, hp.x); ffma2(acc[0][1], w0, hp.y);
            ffma2(acc[1][0], w1, hp.x); ffma2(acc[1][1], w1, hp.y);
            ffma2(acc[2][0], w2, hp.x); ffma2(acc[2][1], w2, hp.y);
            ffma2(acc[3][0], w3, hp.x); ffma2(acc[3][1], w3, hp.y);
            ffma2(acc[4][0], w4, hp.x); ffma2(acc[4][1], w4, hp.y);
            ffma2(acc[5][0], w5, hp.x); ffma2(acc[5][1], w5, hp.y);
            ffma2(acc[6][0], w6, hp.x); ffma2(acc[6][1], w6, hp.y);
            ffma2(acc[7][0], w7, hp.x); ffma2(acc[7][1], w7, hp.y);
        }

        // ---- store partials: s_part[kg][r][b] ----
#pragma unroll
        for (int u = 0; u < 8; ++u) {
            int r = rg * 8 + u;
            *(ulonglong2*)(s_part + (size_t)(kg * 128 + r) * 16 + bq * 4) =
                make_ulonglong2(acc[u][0], acc[u][1]);
        }
        __syncthreads();

        // ---- reduce k-groups + gx (biases folded into gx) -> s_g ----
#pragma unroll
        for (int i = 0; i < 8; ++i) {
            int idx = tid + i * NTHR;
            s_g[idx] = s_gx[idx] + s_part[idx] + s_part[2048 + idx]
                     + s_part[4096 + idx] + s_part[6144 + idx];
        }
        __syncthreads();

        // ---- prefetch gx for step s+1 (independent of h/barrier) ----
        if (s + 1 < Tn) {
            int tn = dir ? (Tn - 2 - s) : (s + 1);
            const float* gxrow = gxb + (size_t)tn * 1024 * Bn;
            for (int i = tid; i < 512; i += NTHR) {
                int r = i >> 2, b4 = (i & 3) * 4;
                int grow = (r >> 5) * Hn + hs * 32 + (r & 31);
                cp_async16(s_gx + r * 16 + b4, gxrow + (size_t)grow * Bn + bg * 16 + b4);
            }
            cp_commit();
        }

        // ---- pointwise: cells tid and tid+256 ----
#pragma unroll
        for (int i = 0; i < 2; ++i) {
            int c = tid + i * NTHR;             // u = c>>4, b = c&15
            float ig = sigmoidf_(s_g[c]);
            float fg = sigmoidf_(s_g[512 + c]);
            float gg = tanhf    (s_g[1024 + c]);
            float og = sigmoidf_(s_g[1536 + c]);
            float cn = fg * c_reg[i] + ig * gg;
            float hn = og * tanhf(cn);
            bool m = (t < len);
            c_reg[i] = m ? cn : c_reg[i];
            float hw = m ? hn : h_reg[i];
            h_reg[i] = hw;
            __stcg(&g_h[(s + 1) & 1][dir][bg][hs * 512 + c], hw);
            if (L0P)
                __stcg(&g_o0[((size_t)t * 512 + dir * Hn + hs * 32 + (c >> 4)) * Bn
                             + bg * 16 + (c & 15)], m ? hn : 0.0f);
        }

        gbar_grp(grp, r_last);
    }
}

// ---------------- FC head ----------------
__global__ void head_kernel(const float* __restrict__ fc1_w, const float* __restrict__ fc1_b,
                            const float* __restrict__ fc2_w, const float* __restrict__ fc2_b,
                            float* __restrict__ out)
{
    __shared__ float s_h[2 * Hn];
    __shared__ float s_r[256];
    int b = blockIdx.x;
    int tid = threadIdx.x;
    int bg = b >> 4, bl = b & 15;
    // final L1 states: 1024 steps -> parity 0
    for (int k = tid; k < 2 * Hn; k += 256) {
        int d = k >> 8;
        int j = k & (Hn - 1);
        s_h[k] = g_h[0][d][bg][j * 16 + bl];
    }
    __syncthreads();

    const float* wr = fc1_w + (size_t)tid * 2 * Hn;
    float sum = fc1_b[tid];
#pragma unroll 8
    for (int k = 0; k < 2 * Hn; ++k) sum += wr[k] * s_h[k];
    s_r[tid] = fmaxf(sum, 0.0f) * fc2_w[tid];
    __syncthreads();
    for (int st = 128; st > 0; st >>= 1) {
        if (tid < st) s_r[tid] += s_r[tid + st];
        __syncthreads();
    }
    if (tid == 0) out[b] = s_r[0] + fc2_b[0];
}

// ---------------- launch ----------------
extern "C" void kernel_launch(void* const* d_in, const int* in_sizes, int n_in,
                              void* d_out, int out_size)
{
    const float* x        = (const float*)d_in[0];
    const int*   lengths  = (const int*)  d_in[1];
    const float* w_ih_l0f = (const float*)d_in[2];
    const float* w_hh_l0f = (const float*)d_in[3];
    const float* b_ih_l0f = (const float*)d_in[4];
    const float* b_hh_l0f = (const float*)d_in[5];
    const float* w_ih_l0b = (const float*)d_in[6];
    const float* w_hh_l0b = (const float*)d_in[7];
    const float* b_ih_l0b = (const float*)d_in[8];
    const float* b_hh_l0b = (const float*)d_in[9];
    const float* w_ih_l1f = (const float*)d_in[10];
    const float* w_hh_l1f = (const float*)d_in[11];
    const float* b_ih_l1f = (const float*)d_in[12];
    const float* b_hh_l1f = (const float*)d_in[13];
    const float* w_ih_l1b = (const float*)d_in[14];
    const float* w_hh_l1b = (const float*)d_in[15];
    const float* b_ih_l1b = (const float*)d_in[16];
    const float* b_hh_l1b = (const float*)d_in[17];
    const float* fc1_w    = (const float*)d_in[18];
    const float* fc1_b    = (const float*)d_in[19];
    const float* fc2_w    = (const float*)d_in[20];
    const float* fc2_b    = (const float*)d_in[21];

    const int rec_smem = RC_SMEM_FLOATS * (int)sizeof(float);   // 200,704 B

    cudaFuncSetAttribute((const void*)rec_kernel<true>,
                         cudaFuncAttributeMaxDynamicSharedMemorySize, rec_smem);
    cudaFuncSetAttribute((const void*)rec_kernel<false>,
                         cudaFuncAttributeMaxDynamicSharedMemorySize, rec_smem);

    transpose_x_kernel<<<(Tn * Dn * Bn + 255) / 256, 256>>>(x);

    dim3 xpgrid(Tn, 8, 2);

    // layer-0 x-projection: g_xT -> g_gx
    xproj_kernel<48, 16, false><<<xpgrid, 128>>>(
        w_ih_l0f, w_ih_l0b, b_ih_l0f, b_hh_l0f, b_ih_l0b, b_hh_l0b);

    // layer-0 recurrence (h-only, consumes gx, writes g_o0)
    rec_kernel<true><<<NBLK, NTHR, rec_smem>>>(w_hh_l0f, w_hh_l0b, lengths);

    // layer-1 x-projection: g_o0 -> g_gx
    xproj_kernel<512, 32, true><<<xpgrid, 128>>>(
        w_ih_l1f, w_ih_l1b, b_ih_l1f, b_hh_l1f, b_ih_l1b, b_hh_l1b);

    // layer-1 recurrence (h-only, consumes gx)
    rec_kernel<false><<<NBLK, NTHR, rec_smem>>>(w_hh_l1f, w_hh_l1b, lengths);

    head_kernel<<<Bn, 256>>>(fc1_w, fc1_b, fc2_w, fc2_b, (float*)d_out);
}